// round 7
// baseline (speedup 1.0000x reference)
#include <cuda_runtime.h>
#include <math.h>

#define NG   512
#define IMGW 224
#define VPIX (IMGW*IMGW)
#define NPIX (3*VPIX)

// Scratch (no cudaMalloc allowed)
__device__ float  g_par[3*NG*8];   // per view, per gaussian: px,py,a,2b,c,w0,0,0
__device__ float  g_d[NPIX];       // depth maps (3 views)
__device__ float  g_t[NPIX];       // blur temp
__device__ double g_acc[2];        // sum, sumsq

// ---------------------------------------------------------------------------
// Per-gaussian preprocessing: iterated cov3d symmetrize/normalize/invert per
// view, projection, global min/max affine mapping -> screen coords.
// ---------------------------------------------------------------------------
__global__ __launch_bounds__(NG) void prep_kernel(const float* __restrict__ pos,
                                                  const float* __restrict__ cov,
                                                  const float* __restrict__ opa,
                                                  const float* __restrict__ imp)
{
    const int n = threadIdx.x;
    if (n == 0) { g_acc[0] = 0.0; g_acc[1] = 0.0; }

    float C00 = cov[n*9+0], C01 = cov[n*9+1], C02 = cov[n*9+2];
    float C10 = cov[n*9+3], C11 = cov[n*9+4], C12 = cov[n*9+5];
    float C20 = cov[n*9+6], C21 = cov[n*9+7], C22 = cov[n*9+8];
    float P[3] = { pos[n*3+0], pos[n*3+1], pos[n*3+2] };
    const float w0 = opa[n] * fminf(fmaxf(imp[n], 0.5f), 2.0f);

    // global min/max of each coordinate over the 512 gaussians
    __shared__ float smn[3][16], smx[3][16];
    __shared__ float bmn[3], bmx[3];
    const int lane = n & 31, wid = n >> 5;
    #pragma unroll
    for (int c = 0; c < 3; c++) {
        float mn = P[c], mx = P[c];
        #pragma unroll
        for (int o = 16; o > 0; o >>= 1) {
            mn = fminf(mn, __shfl_xor_sync(0xffffffffu, mn, o));
            mx = fmaxf(mx, __shfl_xor_sync(0xffffffffu, mx, o));
        }
        if (lane == 0) { smn[c][wid] = mn; smx[c][wid] = mx; }
    }
    __syncthreads();
    if (n == 0) {
        #pragma unroll
        for (int c = 0; c < 3; c++) {
            float mn = smn[c][0], mx = smx[c][0];
            for (int w = 1; w < 16; w++) {
                mn = fminf(mn, smn[c][w]);
                mx = fmaxf(mx, smx[c][w]);
            }
            bmn[c] = mn; bmx[c] = mx;
        }
    }
    __syncthreads();

    const int A0[3] = {0, 0, 2};
    const int A1[3] = {1, 2, 1};

    #pragma unroll
    for (int v = 0; v < 3; v++) {
        // symmetrize + EPS*I  (fp32, matching reference ops/order)
        float t;
        t = 0.5f*(C01 + C10); C01 = t; C10 = t;
        t = 0.5f*(C02 + C20); C02 = t; C20 = t;
        t = 0.5f*(C12 + C21); C12 = t; C21 = t;
        C00 += 1e-6f; C11 += 1e-6f; C22 += 1e-6f;
        float nrm = sqrtf(C00*C00 + C01*C01 + C02*C02 +
                          C10*C10 + C11*C11 + C12*C12 +
                          C20*C20 + C21*C21 + C22*C22);
        float den = nrm + 1e-6f;
        C00 /= den; C01 /= den; C02 /= den;
        C10 /= den; C11 /= den; C12 /= den;
        C20 /= den; C21 /= den; C22 /= den;

        // symmetric 3x3 inverse (cofactor in double for stability)
        double d00 = C00, d01 = C01, d02 = C02, d11 = C11, d12 = C12, d22 = C22;
        double m00 = d11*d22 - d12*d12;
        double m01 = d02*d12 - d01*d22;
        double m02 = d01*d12 - d02*d11;
        double m11 = d00*d22 - d02*d02;
        double m12 = d01*d02 - d00*d12;
        double m22 = d00*d11 - d01*d01;
        double det = d00*m00 + d01*m01 + d02*m02;
        double idet = 1.0 / det;
        float M[9] = { (float)(m00*idet), (float)(m01*idet), (float)(m02*idet),
                       (float)(m01*idet), (float)(m11*idet), (float)(m12*idet),
                       (float)(m02*idet), (float)(m12*idet), (float)(m22*idet) };

        const int a0 = A0[v], a1 = A1[v];
        float a  = M[a0*3+a0] + 1e-10f;
        float b2 = 2.0f * M[a0*3+a1];
        float c  = M[a1*3+a1] + 1e-10f;

        // affine map to [0,111] screen coords (replicating reference fp ops)
        float mnx = bmn[a0], mxx = bmx[a0];
        float mny = bmn[a1], mxy = bmx[a1];
        float rx  = (mxx - mnx) + 1e-6f;
        float m2x = mnx - 0.5f*rx;
        float x2x = mxx + 0.5f*rx;
        float r2x = (x2x - m2x) + 1e-6f;
        float ry  = (mxy - mny) + 1e-6f;
        float m2y = mny - 0.5f*ry;
        float x2y = mxy + 0.5f*ry;
        float r2y = (x2y - m2y) + 1e-6f;
        float px = fminf(fmaxf((P[a0] - m2x) / r2x * 111.0f, 0.0f), 111.0f);
        float py = fminf(fmaxf((P[a1] - m2y) / r2y * 111.0f, 0.0f), 111.0f);

        float* dst = &g_par[(v*NG + n)*8];
        dst[0] = px; dst[1] = py; dst[2] = a; dst[3] = b2;
        dst[4] = c;  dst[5] = w0; dst[6] = 0.0f; dst[7] = 0.0f;
    }
}

// ---------------------------------------------------------------------------
// Splat: per full-res pixel, gather over tile-culled gaussian list.
// exp_full(f) == quad(s) - a*vx - c*vy  (analytic bilinear of a quadratic)
// dm = 0.5*(S - 512*wmin)/(wmax - wmin + eps) + S/(S + eps)
// ---------------------------------------------------------------------------
__global__ __launch_bounds__(256) void splat_kernel()
{
    const int v   = blockIdx.z;
    const int fx0 = blockIdx.x * 16, fy0 = blockIdx.y * 16;
    const int t   = threadIdx.x;
    const int fx  = fx0 + (t & 15), fy = fy0 + (t >> 4);

    float sx, vx;
    if (fx == 0)        { sx = 0.0f;   vx = 0.0f; }
    else if (fx == 223) { sx = 111.0f; vx = 0.0f; }
    else                { sx = (float)fx * 0.5f - 0.25f; vx = 0.1875f; }
    float sy, vy;
    if (fy == 0)        { sy = 0.0f;   vy = 0.0f; }
    else if (fy == 223) { sy = 111.0f; vy = 0.0f; }
    else                { sy = (float)fy * 0.5f - 0.25f; vy = 0.1875f; }
    const float hx = (float)(fx >> 1), hy = (float)(fy >> 1);

    // tile rect in half-res coords for conservative culling
    const float rx0 = (float)(fx0 >> 1), rx1 = (float)((fx0 + 15) >> 1);
    const float ry0 = (float)(fy0 >> 1), ry1 = (float)((fy0 + 15) >> 1);

    __shared__ float sp[NG * 8];
    __shared__ int   wcnt[8];
    __shared__ int   sbase;
    if (t == 0) sbase = 0;

    const float* par  = g_par + v * NG * 8;
    const int    lane = t & 31, wid = t >> 5;

    // deterministic block-ordered compaction of gaussians intersecting tile
    for (int base = 0; base < NG; base += 256) {
        const int n = base + t;
        float px = par[n*8+0], py = par[n*8+1];
        float ddx = fminf(fmaxf(px, rx0), rx1) - px;
        float ddy = fminf(fmaxf(py, ry0), ry1) - py;
        bool keep = (ddx*ddx + ddy*ddy) < 400.0f;
        unsigned m = __ballot_sync(0xffffffffu, keep);
        if (lane == 0) wcnt[wid] = __popc(m);
        __syncthreads();
        int off = sbase;
        for (int w2 = 0; w2 < wid; w2++) off += wcnt[w2];
        if (keep) {
            int slot = off + __popc(m & ((1u << lane) - 1u));
            float4 q0 = *(const float4*)(par + n*8);
            float4 q1 = *(const float4*)(par + n*8 + 4);
            *(float4*)(sp + slot*8)     = q0;
            *(float4*)(sp + slot*8 + 4) = q1;
        }
        __syncthreads();
        if (t == 0) {
            int tot = 0;
            for (int w2 = 0; w2 < 8; w2++) tot += wcnt[w2];
            sbase += tot;
        }
        __syncthreads();
    }
    const int cnt = sbase;

    float S = 0.0f, wmx = -1e30f, wmn = 1e30f;
    for (int i = 0; i < cnt; i++) {
        float4 q0 = *(const float4*)(sp + i*8);   // px,py,a,2b
        float dxh = hx - q0.x, dyh = hy - q0.y;
        float wv = 0.0f;
        if (dxh*dxh + dyh*dyh < 400.0f) {
            float2 q1 = *(const float2*)(sp + i*8 + 4);  // c,w0
            float dx = sx - q0.x, dy = sy - q0.y;
            float e = -(q0.z*(dx*dx + vx) + q0.w*(dx*dy) + q1.x*(dy*dy + vy));
            e = fminf(fmaxf(e, -20.0f), 0.0f);
            wv = q1.y * __expf(e);
        }
        S   += wv;
        wmx  = fmaxf(wmx, wv);
        wmn  = fminf(wmn, wv);
    }
    // culled gaussians contribute exactly zero to min/max/sum
    if (cnt < NG) { wmn = fminf(wmn, 0.0f); wmx = fmaxf(wmx, 0.0f); }

    float dm = 0.5f*(S - 512.0f*wmn)/((wmx - wmn) + 1e-6f) + S/(S + 1e-6f);
    g_d[v*VPIX + fy*IMGW + fx] = dm;
}

// ---------------------------------------------------------------------------
// 7-tap gaussian blur (sigma=1, r=3, zero pad) + fill (where d>1e-6 keep d)
// ---------------------------------------------------------------------------
__device__ __forceinline__ void blur_weights(float& K0, float& K1, float& K2, float& K3)
{
    const double E1 = 0.60653065971263342;   // exp(-0.5)
    const double E2 = 0.13533528323661270;   // exp(-2.0)
    const double E3 = 0.011108996538242306;  // exp(-4.5)
    const double KS = 1.0 + 2.0*(E1 + E2 + E3);
    K0 = (float)(1.0/KS); K1 = (float)(E1/KS); K2 = (float)(E2/KS); K3 = (float)(E3/KS);
}

__global__ __launch_bounds__(256) void blurH_kernel()
{
    int i = blockIdx.x*256 + threadIdx.x;
    if (i >= NPIX) return;
    int y = (i / IMGW) % IMGW;
    float K0,K1,K2,K3; blur_weights(K0,K1,K2,K3);
    float acc = K0 * g_d[i];
    if (y >= 1)   acc += K1 * g_d[i - 1*IMGW];
    if (y >= 2)   acc += K2 * g_d[i - 2*IMGW];
    if (y >= 3)   acc += K3 * g_d[i - 3*IMGW];
    if (y <= 222) acc += K1 * g_d[i + 1*IMGW];
    if (y <= 221) acc += K2 * g_d[i + 2*IMGW];
    if (y <= 220) acc += K3 * g_d[i + 3*IMGW];
    g_t[i] = acc;
}

__global__ __launch_bounds__(256) void blurW_merge_kernel()
{
    int i = blockIdx.x*256 + threadIdx.x;
    if (i >= NPIX) return;
    int x = i % IMGW;
    float K0,K1,K2,K3; blur_weights(K0,K1,K2,K3);
    float acc = K0 * g_t[i];
    if (x >= 1)   acc += K1 * g_t[i - 1];
    if (x >= 2)   acc += K2 * g_t[i - 2];
    if (x >= 3)   acc += K3 * g_t[i - 3];
    if (x <= 222) acc += K1 * g_t[i + 1];
    if (x <= 221) acc += K2 * g_t[i + 2];
    if (x <= 220) acc += K3 * g_t[i + 3];
    float dv = g_d[i];
    g_d[i] = (dv > 1e-6f) ? dv : acc;
}

// ---------------------------------------------------------------------------
// Global mean / std(ddof=1) normalize
// ---------------------------------------------------------------------------
__global__ __launch_bounds__(256) void stats_kernel()
{
    int i = blockIdx.x*256 + threadIdx.x;
    float x = (i < NPIX) ? g_d[i] : 0.0f;
    double s  = (double)x;
    double s2 = (double)x * (double)x;
    #pragma unroll
    for (int o = 16; o > 0; o >>= 1) {
        s  += __shfl_down_sync(0xffffffffu, s,  o);
        s2 += __shfl_down_sync(0xffffffffu, s2, o);
    }
    __shared__ double ws[8], ws2[8];
    int lane = threadIdx.x & 31, wid = threadIdx.x >> 5;
    if (lane == 0) { ws[wid] = s; ws2[wid] = s2; }
    __syncthreads();
    if (threadIdx.x == 0) {
        double a = 0.0, b = 0.0;
        for (int w = 0; w < 8; w++) { a += ws[w]; b += ws2[w]; }
        atomicAdd(&g_acc[0], a);
        atomicAdd(&g_acc[1], b);
    }
}

__global__ __launch_bounds__(256) void norm_kernel(float* __restrict__ out)
{
    int i = blockIdx.x*256 + threadIdx.x;
    if (i >= NPIX) return;
    double s1 = g_acc[0], s2 = g_acc[1];
    double mean = s1 / (double)NPIX;
    double var  = (s2 - s1*mean) / (double)(NPIX - 1);
    float stdf  = (float)sqrt(fmax(var, 0.0));
    out[i] = (g_d[i] - (float)mean) / (stdf + 1e-6f);
}

// ---------------------------------------------------------------------------
extern "C" void kernel_launch(void* const* d_in, const int* in_sizes, int n_in,
                              void* d_out, int out_size)
{
    const float* pos = (const float*)d_in[0];  // (1,512,3)
    const float* cov = (const float*)d_in[1];  // (1,512,3,3)
    const float* opa = (const float*)d_in[2];  // (1,512)
    const float* imp = (const float*)d_in[3];  // (1,1000)

    prep_kernel<<<1, NG>>>(pos, cov, opa, imp);

    dim3 g(IMGW/16, IMGW/16, 3);
    splat_kernel<<<g, 256>>>();

    const int nb = (NPIX + 255) / 256;
    for (int s = 0; s < 2; s++) {
        blurH_kernel<<<nb, 256>>>();
        blurW_merge_kernel<<<nb, 256>>>();
    }
    stats_kernel<<<nb, 256>>>();
    norm_kernel<<<nb, 256>>>((float*)d_out);
}